// round 5
// baseline (speedup 1.0000x reference)
#include <cuda_runtime.h>
#include <math_constants.h>

#define NTRK 4096
#define NB 64
#define NBINS (NB * NB)
#define FULLMASK 0xffffffffu
#define BUILD_THREADS 1024
#define SEARCH_WARPS 8
#define SEARCH_THREADS (SEARCH_WARPS * 32)

// ---- device scratch (static: no allocation) ----
__device__ float  g_minx, g_miny, g_invx, g_invy, g_cwx, g_cwy;
__device__ int    g_ofs[NBINS + 1];
__device__ float2 g_pxy[NTRK];
__device__ int    g_pid[NTRK];

// lexicographic (d2, idx) insert into a sorted-4 list (s0<=s1<=s2<=s3).
// Exact tie-break to smaller original index == jax top_k stability.
#define LESSI(da, ja, db, jb) (((da) < (db)) || ((da) == (db) && (ja) < (jb)))
#define LEX_INSERT(dv, jv)                                         \
    if (LESSI(dv, jv, s3, i3)) {                                   \
        if (LESSI(dv, jv, s1, i1)) {                               \
            s3 = s2; i3 = i2; s2 = s1; i2 = i1;                    \
            if (LESSI(dv, jv, s0, i0)) { s1 = s0; i1 = i0; s0 = (dv); i0 = (jv); } \
            else                       { s1 = (dv); i1 = (jv); }   \
        } else {                                                   \
            if (LESSI(dv, jv, s2, i2)) { s3 = s2; i3 = i2; s2 = (dv); i2 = (jv); } \
            else                       { s3 = (dv); i3 = (jv); }   \
        }                                                          \
    }

// scan all points of cell (ccx, ccy), lex-insert non-self candidates
#define PROC_CELL(ccx, ccy)                                        \
    do {                                                           \
        if ((unsigned)(ccx) < NB && (unsigned)(ccy) < NB) {        \
            int c_ = (ccy) * NB + (ccx);                           \
            int pb_ = g_ofs[c_], pe_ = g_ofs[c_ + 1];              \
            for (int p_ = pb_; p_ < pe_; ++p_) {                   \
                float2 pt_ = g_pxy[p_];                            \
                int pj_ = g_pid[p_];                               \
                float dx_ = pt_.x - q.x, dy_ = pt_.y - q.y;        \
                float dd_ = fmaf(dx_, dx_, dy_ * dy_);             \
                if (pj_ != i) { LEX_INSERT(dd_, pj_); }            \
            }                                                      \
        }                                                          \
    } while (0)

// ============================================================================
// Kernel 1: fused grid build (single block) — bbox, histogram, scan, scatter
// ============================================================================
__global__ __launch_bounds__(BUILD_THREADS)
void build_kernel(const float2* __restrict__ obs2, int n)
{
    __shared__ int   s_cnt[NBINS];          // 16 KB histogram / cursors
    __shared__ int   s_tot[BUILD_THREADS];  // scan scratch
    __shared__ float s_red[128];            // bbox reduce scratch
    __shared__ float s_par[4];              // minx, miny, invx, invy

    const int t    = threadIdx.x;
    const int lane = t & 31;
    const int warp = t >> 5;

    // load up to 4 points per thread
    float px[4] = {0, 0, 0, 0}, py[4] = {0, 0, 0, 0};
    float mnx = CUDART_INF_F, mxx = -CUDART_INF_F;
    float mny = CUDART_INF_F, mxy = -CUDART_INF_F;
    #pragma unroll
    for (int k = 0; k < 4; ++k) {
        int p = t + k * BUILD_THREADS;
        if (p < n) {
            float2 v = obs2[p];
            px[k] = v.x; py[k] = v.y;
            mnx = fminf(mnx, v.x); mxx = fmaxf(mxx, v.x);
            mny = fminf(mny, v.y); mxy = fmaxf(mxy, v.y);
        }
    }

    // bbox: warp reduce then cross-warp reduce
    #pragma unroll
    for (int off = 16; off > 0; off >>= 1) {
        mnx = fminf(mnx, __shfl_xor_sync(FULLMASK, mnx, off));
        mxx = fmaxf(mxx, __shfl_xor_sync(FULLMASK, mxx, off));
        mny = fminf(mny, __shfl_xor_sync(FULLMASK, mny, off));
        mxy = fmaxf(mxy, __shfl_xor_sync(FULLMASK, mxy, off));
    }
    if (lane == 0) {
        s_red[warp]      = mnx;
        s_red[32 + warp] = mxx;
        s_red[64 + warp] = mny;
        s_red[96 + warp] = mxy;
    }
    // zero histogram while bbox settles
    for (int c = t; c < NBINS; c += BUILD_THREADS) s_cnt[c] = 0;
    __syncthreads();

    if (warp == 0) {
        float a  = s_red[lane];
        float b_ = s_red[32 + lane];
        float c  = s_red[64 + lane];
        float d  = s_red[96 + lane];
        #pragma unroll
        for (int off = 16; off > 0; off >>= 1) {
            a  = fminf(a,  __shfl_xor_sync(FULLMASK, a,  off));
            b_ = fmaxf(b_, __shfl_xor_sync(FULLMASK, b_, off));
            c  = fminf(c,  __shfl_xor_sync(FULLMASK, c,  off));
            d  = fmaxf(d,  __shfl_xor_sync(FULLMASK, d,  off));
        }
        if (lane == 0) {
            float wx = fmaxf(b_ - a, 1e-30f);
            float wy = fmaxf(d - c, 1e-30f);
            float invx = (float)NB / wx, invy = (float)NB / wy;
            g_minx = a; g_miny = c;
            g_invx = invx; g_invy = invy;
            g_cwx = wx / (float)NB; g_cwy = wy / (float)NB;
            s_par[0] = a; s_par[1] = c; s_par[2] = invx; s_par[3] = invy;
        }
    }
    __syncthreads();

    const float minx = s_par[0], miny = s_par[1];
    const float invx = s_par[2], invy = s_par[3];

    // histogram (smem atomics)
    int bins[4] = {0, 0, 0, 0};
    #pragma unroll
    for (int k = 0; k < 4; ++k) {
        int p = t + k * BUILD_THREADS;
        if (p < n) {
            int bx = min(NB - 1, max(0, (int)((px[k] - minx) * invx)));
            int by = min(NB - 1, max(0, (int)((py[k] - miny) * invy)));
            bins[k] = by * NB + bx;
            atomicAdd(&s_cnt[bins[k]], 1);
        }
    }
    __syncthreads();

    // exclusive scan of 4096 counts: 4 per thread + Hillis-Steele over 1024
    int c4[4];
    #pragma unroll
    for (int k = 0; k < 4; ++k) c4[k] = s_cnt[4 * t + k];
    int tot = c4[0] + c4[1] + c4[2] + c4[3];
    s_tot[t] = tot;
    __syncthreads();
    for (int off = 1; off < BUILD_THREADS; off <<= 1) {
        int v = (t >= off) ? s_tot[t - off] : 0;
        __syncthreads();
        s_tot[t] += v;
        __syncthreads();
    }
    int run = s_tot[t] - tot;   // exclusive prefix
    int cur[4];
    #pragma unroll
    for (int k = 0; k < 4; ++k) {
        g_ofs[4 * t + k] = run;
        cur[k] = run;
        run += c4[k];
    }
    if (t == BUILD_THREADS - 1) g_ofs[NBINS] = run;
    __syncthreads();
    #pragma unroll
    for (int k = 0; k < 4; ++k) s_cnt[4 * t + k] = cur[k];  // become cursors
    __syncthreads();

    // scatter
    #pragma unroll
    for (int k = 0; k < 4; ++k) {
        int p = t + k * BUILD_THREADS;
        if (p < n) {
            int pos = atomicAdd(&s_cnt[bins[k]], 1);
            g_pxy[pos] = make_float2(px[k], py[k]);
            g_pid[pos] = p;
        }
    }
}

// ============================================================================
// Kernel 2: one warp per track — expanding ring kNN + fused Linear/ReLU
// ============================================================================
__global__ __launch_bounds__(SEARCH_THREADS)
void search_kernel(const float2* __restrict__ obs1,
                   const float2* __restrict__ obs2,
                   const float* __restrict__ W,
                   const float* __restrict__ bias,
                   float* __restrict__ out,
                   int n)
{
    const int lane = threadIdx.x & 31;
    const int i = blockIdx.x * SEARCH_WARPS + (threadIdx.x >> 5);
    if (i >= n) return;

    const float2 q = obs2[i];
    const float minx = g_minx, miny = g_miny;
    const float invx = g_invx, invy = g_invy;
    const float cwx  = g_cwx,  cwy  = g_cwy;

    const int cx = min(NB - 1, max(0, (int)((q.x - minx) * invx)));
    const int cy = min(NB - 1, max(0, (int)((q.y - miny) * invy)));

    float s0 = CUDART_INF_F, s1 = CUDART_INF_F, s2 = CUDART_INF_F, s3 = CUDART_INF_F;
    int   i0 = n, i1 = n, i2 = n, i3 = n;

    // initial 3x3 window (rings 0..1), one cell per lane
    for (int p = lane; p < 9; p += 32)
        PROC_CELL(cx + p % 3 - 1, cy + p / 3 - 1);

    const float eps = (cwx + cwy) * 0.001f;   // binning-rounding safety margin
    int rad = 1;
    while (true) {
        // min distance from q to any point outside the processed window;
        // sides at/beyond the grid edge contribute +inf (no points there)
        float bl = (cx - rad > 0)      ? (q.x - (minx + (float)(cx - rad) * cwx))     : CUDART_INF_F;
        float br = (cx + rad < NB - 1) ? ((minx + (float)(cx + rad + 1) * cwx) - q.x) : CUDART_INF_F;
        float bd = (cy - rad > 0)      ? (q.y - (miny + (float)(cy - rad) * cwy))     : CUDART_INF_F;
        float bu = (cy + rad < NB - 1) ? ((miny + (float)(cy + rad + 1) * cwy) - q.y) : CUDART_INF_F;
        float bmin = fminf(fminf(bl, br), fminf(bd, bu));

        int done;
        if (isinf(bmin)) {
            done = 1;  // window covers entire grid: everything processed
        } else {
            float be = fmaxf(bmin - eps, 0.0f);
            float b2 = be * be;
            // exact: warp has >=4 candidates with d2 <= b2  <=>  global 4th <= b2
            int cnt = (s3 <= b2) ? 4 : (s2 <= b2) ? 3 : (s1 <= b2) ? 2 : (s0 <= b2) ? 1 : 0;
            done = (__reduce_add_sync(FULLMASK, cnt) >= 4);
        }
        if (done) break;

        ++rad;
        const int per = 8 * rad, twor = 2 * rad;
        for (int p = lane; p < per; p += 32) {
            int side = p / twor, o = p % twor;
            int dx, dy;
            if      (side == 0) { dx = -rad + o; dy = -rad; }
            else if (side == 1) { dx =  rad;     dy = -rad + o; }
            else if (side == 2) { dx =  rad - o; dy =  rad; }
            else                { dx = -rad;     dy =  rad - o; }
            PROC_CELL(cx + dx, cy + dy);
        }
    }

    // butterfly merge: every lane ends with identical global top-4
    #pragma unroll
    for (int off = 16; off > 0; off >>= 1) {
        float t0 = __shfl_xor_sync(FULLMASK, s0, off);
        float t1 = __shfl_xor_sync(FULLMASK, s1, off);
        float t2 = __shfl_xor_sync(FULLMASK, s2, off);
        float t3 = __shfl_xor_sync(FULLMASK, s3, off);
        int   u0 = __shfl_xor_sync(FULLMASK, i0, off);
        int   u1 = __shfl_xor_sync(FULLMASK, i1, off);
        int   u2 = __shfl_xor_sync(FULLMASK, i2, off);
        int   u3 = __shfl_xor_sync(FULLMASK, i3, off);
        LEX_INSERT(t0, u0);
        LEX_INSERT(t1, u1);
        LEX_INSERT(t2, u2);
        LEX_INSERT(t3, u3);
    }

    // epilogue: lane = k*8 + e computes out[i][k*8 + e]
    const int k = lane >> 3;
    const int e = lane & 7;
    int nj = (k == 0) ? i0 : (k == 1) ? i1 : (k == 2) ? i2 : i3;
    if (nj >= n) nj = (i == 0) ? 1 : 0;   // degenerate-n safety

    float2 pj  = obs2[nj];
    float2 o1j = obs1[nj];
    float2 o1i = obs1[i];

    float rpx = pj.x - q.x;
    float rpy = pj.y - q.y;
    float rvx = (pj.x - o1j.x) - (q.x - o1i.x);
    float rvy = (pj.y - o1j.y) - (q.y - o1i.y);

    float acc = bias[e];
    acc = fmaf(rpx, W[0 * 8 + e], acc);
    acc = fmaf(rpy, W[1 * 8 + e], acc);
    acc = fmaf(rvx, W[2 * 8 + e], acc);
    acc = fmaf(rvy, W[3 * 8 + e], acc);

    out[i * 32 + lane] = fmaxf(acc, 0.0f);
}

extern "C" void kernel_launch(void* const* d_in, const int* in_sizes, int n_in,
                              void* d_out, int out_size) {
    const float2* obs1 = (const float2*)d_in[0];  // [N, 2]
    const float2* obs2 = (const float2*)d_in[1];  // [N, 2]
    const float*  W    = (const float*)d_in[2];   // [4, 8]
    const float*  b    = (const float*)d_in[3];   // [8]
    float* out = (float*)d_out;                    // [N, 32]

    int n = in_sizes[0] / 2;
    if (n > NTRK) n = NTRK;

    build_kernel<<<1, BUILD_THREADS>>>(obs2, n);
    int blocks = (n + SEARCH_WARPS - 1) / SEARCH_WARPS;
    search_kernel<<<blocks, SEARCH_THREADS>>>(obs1, obs2, W, b, out, n);
}